// round 7
// baseline (speedup 1.0000x reference)
#include <cuda_runtime.h>
#include <cuda_bf16.h>
#include <math.h>

#define CM 64
#define NA 512
#define MS 32768
#define KS 5
#define HW 4096
#define CHW 262144
#define NUMEL 2097152.0f
#define FULL 0xffffffffu

typedef unsigned long long u64;

// packed fp32x2 helpers (sm_103a; ptxas never emits these on its own)
#define F32X2_FMA(d, a, b) \
    asm("fma.rn.f32x2 %0, %1, %2, %0;" : "+l"(d) : "l"(a), "l"(b))
#define F32X2_MUL(d, a, b) \
    asm("mul.rn.f32x2 %0, %1, %2;" : "=l"(d) : "l"(a), "l"(b))
#define F32X2_ADD(d, a, b) \
    asm("add.rn.f32x2 %0, %1, %2;" : "=l"(d) : "l"(a), "l"(b))
#define F32X2_DUP(d, x) \
    asm("mov.b64 %0, {%1, %1};" : "=l"(d) : "r"(__float_as_uint(x)))

__device__ __forceinline__ float u64_lo(u64 v) { return __uint_as_float((unsigned)v); }
__device__ __forceinline__ float u64_hi(u64 v) { return __uint_as_float((unsigned)(v >> 32)); }

__device__ float g_DnT[NA * CM];
__device__ float g_Dn[CM * NA];
__device__ float g_G[NA * NA];
__device__ float g_H[(size_t)MS * NA];
__device__ float g_partial[8192];

// ---------------------------------------------------------------------------
// Kernel 1: normalize dictionary columns, write both layouts
// ---------------------------------------------------------------------------
__global__ void k_norm(const float* __restrict__ dict) {
    int n = blockIdx.x * blockDim.x + threadIdx.x;
    if (n >= NA) return;
    float s = 0.f;
    #pragma unroll
    for (int c = 0; c < CM; c++) {
        float v = dict[c * NA + n];
        s += v * v;
    }
    float inv = 1.f / fmaxf(sqrtf(s), 1e-10f);
    #pragma unroll
    for (int c = 0; c < CM; c++) {
        float v = dict[c * NA + n] * inv;
        g_DnT[n * CM + c] = v;
        g_Dn[c * NA + n] = v;
    }
}

// ---------------------------------------------------------------------------
// Kernel 2: Gram matrix G = Dn^T Dn
// ---------------------------------------------------------------------------
__global__ void k_gram() {
    __shared__ float di[CM];
    int i = blockIdx.x;
    if (threadIdx.x < CM / 4)
        ((float4*)di)[threadIdx.x] = ((const float4*)(g_DnT + i * CM))[threadIdx.x];
    __syncthreads();
    for (int j = threadIdx.x; j < NA; j += blockDim.x) {
        const float4* dj = (const float4*)(g_DnT + j * CM);
        float s = 0.f;
        #pragma unroll
        for (int c = 0; c < CM / 4; c++) {
            float4 v = dj[c];
            s += di[c * 4 + 0] * v.x + di[c * 4 + 1] * v.y
               + di[c * 4 + 2] * v.z + di[c * 4 + 3] * v.w;
        }
        g_G[(size_t)i * NA + j] = s;
    }
}

// ---------------------------------------------------------------------------
// Kernel 3: H = X^T Dn. 128x128 tiles, K-tile=32, 8x8 blocking via FFMA2.
// ---------------------------------------------------------------------------
__global__ __launch_bounds__(256, 2) void k_gemm(const float* __restrict__ ze) {
    __shared__ float As[32][128];
    __shared__ float Bs[32][128];
    int tx = threadIdx.x & 15, ty = threadIdx.x >> 4;
    int m0 = blockIdx.y * 128, n0 = blockIdx.x * 128;
    int bb = m0 >> 12;
    int p0 = m0 & (HW - 1);
    const float* zb = ze + (size_t)bb * CHW + p0;

    u64 acc2[8][4];
    #pragma unroll
    for (int i = 0; i < 8; i++)
        #pragma unroll
        for (int j = 0; j < 4; j++) acc2[i][j] = 0ull;

    #pragma unroll
    for (int kk0 = 0; kk0 < CM; kk0 += 32) {
        #pragma unroll
        for (int r = 0; r < 4; r++) {
            int idx = r * 256 + threadIdx.x;
            int kk = idx >> 5, m4 = (idx & 31) << 2;
            *(float4*)&As[kk][m4] = *(const float4*)(zb + (size_t)(kk0 + kk) * HW + m4);
            *(float4*)&Bs[kk][m4] = *(const float4*)(g_Dn + (size_t)(kk0 + kk) * NA + n0 + m4);
        }
        __syncthreads();
        #pragma unroll
        for (int k = 0; k < 32; k++) {
            float4 a0 = *(float4*)&As[k][ty * 8];
            float4 a1 = *(float4*)&As[k][ty * 8 + 4];
            ulonglong2 bp0 = *(ulonglong2*)&Bs[k][tx * 8];
            ulonglong2 bp1 = *(ulonglong2*)&Bs[k][tx * 8 + 4];
            float ar[8] = {a0.x, a0.y, a0.z, a0.w, a1.x, a1.y, a1.z, a1.w};
            u64 bp[4] = {bp0.x, bp0.y, bp1.x, bp1.y};
            #pragma unroll
            for (int i = 0; i < 8; i++) {
                u64 ad;
                F32X2_DUP(ad, ar[i]);
                #pragma unroll
                for (int j = 0; j < 4; j++)
                    F32X2_FMA(acc2[i][j], ad, bp[j]);
            }
        }
        __syncthreads();
    }
    #pragma unroll
    for (int i = 0; i < 8; i++) {
        int m = m0 + ty * 8 + i;
        u64* o = (u64*)&g_H[(size_t)m * NA + n0 + tx * 8];
        ulonglong2 s0, s1;
        s0.x = acc2[i][0]; s0.y = acc2[i][1];
        s1.x = acc2[i][2]; s1.y = acc2[i][3];
        *(ulonglong2*)o       = s0;
        *(ulonglong2*)(o + 2) = s1;
    }
}

// ---------------------------------------------------------------------------
// Kernel 4: OMP + fused reconstruction. One warp per signal, 4 per CTA.
// Cheap argmax: per-element FMNMX value tracking, REDUX + equality-scan
// index recovery. h_bar[bi] loaded directly (uniform, L1-hot).
// ---------------------------------------------------------------------------
__global__ __launch_bounds__(128, 5) void k_omp(const float* __restrict__ ze,
                                                float* __restrict__ out_zdl,
                                                float* __restrict__ out_sup,
                                                float* __restrict__ out_cf) {
    __shared__ float tile[CM][5];   // [channel][signal] padded: conflict-free
    __shared__ float errs[2];

    const int lane = threadIdx.x & 31;
    const int wid  = threadIdx.x >> 5;
    const int m = blockIdx.x * 4 + wid;
    const float* Hb = g_H + (size_t)m * NA;
    const ulonglong2* Hb2 = (const ulonglong2*)Hb;

    u64   h2[8];          // 16 h values as 8 pairs; pair 2j+q covers elems 4*(lane+32j)+2q+{0,1}
    u64   R2[3][8];       // cached G rows for selected atoms 0..2
    float Lo[10];         // off-diagonal L rows 1..4 (packed (i-1)i/2+j)
    float Linv[5];        // reciprocal diagonals
    float y[5];
    float gam[5];
    int   sel[5];

    // load h_bar + value-only max tracking (FMNMX with free |.| modifiers)
    float bv = 0.f;
#pragma unroll
    for (int j = 0; j < 4; j++) {
        ulonglong2 v = __ldg(&Hb2[lane + 32 * j]);
        h2[2 * j] = v.x;
        h2[2 * j + 1] = v.y;
        bv = fmaxf(bv, fabsf(u64_lo(v.x)));
        bv = fmaxf(bv, fabsf(u64_hi(v.x)));
        bv = fmaxf(bv, fabsf(u64_lo(v.y)));
        bv = fmaxf(bv, fabsf(u64_hi(v.y)));
    }

#pragma unroll
    for (int k = 1; k <= KS; k++) {
        // ---- warp max value, then lowest-index recovery
        float wmax = __uint_as_float(__reduce_max_sync(FULL, __float_as_uint(bv)));
        int cand = 1 << 30;
#pragma unroll
        for (int j = 3; j >= 0; j--) {        // descending index: lowest wins
            int base = 4 * (lane + 32 * j);
            u64 px = h2[2 * j], py = h2[2 * j + 1];
            if (fabsf(u64_hi(py)) == wmax) cand = base + 3;
            if (fabsf(u64_lo(py)) == wmax) cand = base + 2;
            if (fabsf(u64_hi(px)) == wmax) cand = base + 1;
            if (fabsf(u64_lo(px)) == wmax) cand = base;
        }
        int bi = __reduce_min_sync(FULL, cand);

        const float* Grow = g_G + (size_t)bi * NA;

        // true h_bar[bi]: uniform broadcast load, L1-hot (row loaded at start)
        float hbv = __ldg(Hb + bi);

        // ---- uniform broadcast loads: Gv[t] = G[bi][sel_t] (L2-hot)
        float Gv[4];
#pragma unroll
        for (int t = 0; t < 4; t++)
            if (t < k - 1) Gv[t] = __ldg(Grow + sel[t]);

        // ---- Cholesky rank-1 extension (divide-free, all lanes uniform)
        if (k > 1) {
            float w[4], ww = 0.f;
#pragma unroll
            for (int i = 0; i < 4; i++) {
                if (i < k - 1) {
                    float a = Gv[i];
#pragma unroll
                    for (int j = 0; j < 4; j++)
                        if (j < i) a -= Lo[(i - 1) * i / 2 + j] * w[j];
                    if (i > 0) a *= Linv[i];
                    w[i] = a;
                    ww += a * a;
                }
            }
            const int r = k - 1;
#pragma unroll
            for (int j = 0; j < 4; j++)
                if (j < r) Lo[(r - 1) * r / 2 + j] = w[j];
            Linv[r] = rsqrtf(fmaxf(1.f - ww, 1e-12f));
        } else {
            Linv[0] = 1.f;
        }
        sel[k - 1] = bi;

        // ---- incremental forward solve: only y[k-1] is new
        {
            const int i = k - 1;
            float a = hbv;
#pragma unroll
            for (int j = 0; j < 4; j++)
                if (j < i) a -= Lo[(i - 1) * i / 2 + j] * y[j];
            y[i] = a * Linv[i];
        }

        // ---- backward solve: L^T g2 = y
        float g2[5];
#pragma unroll
        for (int i = 4; i >= 0; i--) {
            if (i < k) {
                float a = y[i];
#pragma unroll
                for (int j = 0; j < 5; j++)
                    if (j > i && j < k) a -= Lo[(j - 1) * j / 2 + i] * g2[j];
                g2[i] = a * Linv[i];
            }
        }
        float dg[5];
#pragma unroll
        for (int i = 0; i < 5; i++) {
            if (i < k) {
                float old = (i < k - 1) ? gam[i] : 0.f;
                dg[i] = g2[i] - old;
                gam[i] = g2[i];
            }
        }

        // ---- fused packed h update + value-only max tracking
        if (k < KS) {
            const ulonglong2* Gr2 = (const ulonglong2*)Grow;
            u64 ndp[4];
#pragma unroll
            for (int t = 0; t < 4; t++)
                if (t < k) F32X2_DUP(ndp[t], -dg[t]);
            bv = 0.f;
#pragma unroll
            for (int j = 0; j < 4; j++) {
                ulonglong2 gv = __ldg(&Gr2[lane + 32 * j]);
#pragma unroll
                for (int q = 0; q < 2; q++) {
                    u64 gp = q ? gv.y : gv.x;
                    int p = 2 * j + q;
                    if (k - 1 < 3) R2[k - 1 < 3 ? k - 1 : 0][p] = gp;
                    u64 a;
                    F32X2_MUL(a, ndp[k - 1], gp);
#pragma unroll
                    for (int t = 0; t < 3; t++)
                        if (t < k - 1) F32X2_FMA(a, ndp[t], R2[t][p]);
                    u64 hn;
                    F32X2_ADD(hn, h2[p], a);
                    h2[p] = hn;
                    bv = fmaxf(bv, fabsf(u64_lo(hn)));
                    bv = fmaxf(bv, fabsf(u64_hi(hn)));
                }
            }
        }
    }

    // ---- support / coeff outputs (values are warp-uniform)
    if (lane < KS) {
        float s = (lane == 0) ? (float)sel[0] :
                  (lane == 1) ? (float)sel[1] :
                  (lane == 2) ? (float)sel[2] :
                  (lane == 3) ? (float)sel[3] : (float)sel[4];
        float c = (lane == 0) ? gam[0] :
                  (lane == 1) ? gam[1] :
                  (lane == 2) ? gam[2] :
                  (lane == 3) ? gam[3] : gam[4];
        out_sup[(size_t)m * KS + lane] = s;
        out_cf[(size_t)m * KS + lane]  = c;
    }

    // ---- fused reconstruction: warp computes channels (coalesced DnT reads)
#pragma unroll
    for (int half = 0; half < 2; half++) {
        int c = lane + 32 * half;
        float r = 0.f;
#pragma unroll
        for (int t = 0; t < KS; t++)
            r = fmaf(gam[t], g_DnT[sel[t] * CM + c], r);
        tile[c][wid] = r;
    }
    __syncthreads();

    // ---- write phase: 64 threads, one channel each, float4 over 4 pixels
    int b  = (blockIdx.x * 4) >> 12;
    int p0 = (blockIdx.x * 4) & (HW - 1);
    float err = 0.f;
    if (threadIdx.x < CM) {
        int c = threadIdx.x;
        float4 v = make_float4(tile[c][0], tile[c][1], tile[c][2], tile[c][3]);
        size_t zi = (size_t)b * CHW + (size_t)c * HW + p0;
        float4 x = *(const float4*)(ze + zi);
        float d0 = v.x - x.x, d1 = v.y - x.y, d2 = v.z - x.z, d3 = v.w - x.w;
        err = d0 * d0 + d1 * d1 + d2 * d2 + d3 * d3;
        *(float4*)(out_zdl + zi) = v;
    }
#pragma unroll
    for (int off = 16; off; off >>= 1)
        err += __shfl_down_sync(FULL, err, off);
    if (lane == 0 && wid < 2) errs[wid] = err;
    __syncthreads();
    if (threadIdx.x == 0) g_partial[blockIdx.x] = errs[0] + errs[1];
}

// ---------------------------------------------------------------------------
// Kernel 5: deterministic loss reduction. loss = 1.25 * MSE
// ---------------------------------------------------------------------------
__global__ void k_loss(float* __restrict__ out_loss) {
    __shared__ float red[256];
    float s = 0.f;
    for (int i = threadIdx.x; i < 8192; i += 256) s += g_partial[i];
    red[threadIdx.x] = s;
    __syncthreads();
    for (int o = 128; o; o >>= 1) {
        if (threadIdx.x < o) red[threadIdx.x] += red[threadIdx.x + o];
        __syncthreads();
    }
    if (threadIdx.x == 0) out_loss[0] = 1.25f * red[0] / NUMEL;
}

// ---------------------------------------------------------------------------
extern "C" void kernel_launch(void* const* d_in, const int* in_sizes, int n_in,
                              void* d_out, int out_size) {
    const float* ze   = (const float*)d_in[0];
    const float* dict = (const float*)d_in[1];
    float* out = (float*)d_out;
    float* out_zdl  = out;
    float* out_loss = out + 2097152;
    float* out_sup  = out + 2097153;
    float* out_cf   = out + 2097153 + 163840;

    k_norm<<<2, 256>>>(dict);
    k_gram<<<NA, 128>>>();
    dim3 g(NA / 128, MS / 128);
    k_gemm<<<g, 256>>>(ze);
    k_omp<<<MS / 4, 128>>>(ze, out_zdl, out_sup, out_cf);
    k_loss<<<1, 256>>>(out_loss);
}

// round 8
// speedup vs baseline: 1.0993x; 1.0993x over previous
#include <cuda_runtime.h>
#include <cuda_bf16.h>
#include <math.h>

#define CM 64
#define NA 512
#define MS 32768
#define KS 5
#define HW 4096
#define CHW 262144
#define NUMEL 2097152.0f
#define FULL 0xffffffffu

typedef unsigned long long u64;

// packed fp32x2 helpers (sm_103a; ptxas never emits these on its own)
#define F32X2_FMA(d, a, b) \
    asm("fma.rn.f32x2 %0, %1, %2, %0;" : "+l"(d) : "l"(a), "l"(b))
#define F32X2_MUL(d, a, b) \
    asm("mul.rn.f32x2 %0, %1, %2;" : "=l"(d) : "l"(a), "l"(b))
#define F32X2_ADD(d, a, b) \
    asm("add.rn.f32x2 %0, %1, %2;" : "=l"(d) : "l"(a), "l"(b))
#define F32X2_DUP(d, x) \
    asm("mov.b64 %0, {%1, %1};" : "=l"(d) : "r"(__float_as_uint(x)))

__device__ __forceinline__ float u64_lo(u64 v) { return __uint_as_float((unsigned)v); }
__device__ __forceinline__ float u64_hi(u64 v) { return __uint_as_float((unsigned)(v >> 32)); }

__device__ float g_DnT[NA * CM];
__device__ float g_Dn[CM * NA];
__device__ float g_G[NA * NA];
__device__ float g_H[(size_t)MS * NA];
__device__ float g_partial[1024];

// ---------------------------------------------------------------------------
// Kernel 1: normalize dictionary columns, write both layouts
// ---------------------------------------------------------------------------
__global__ void k_norm(const float* __restrict__ dict) {
    int n = blockIdx.x * blockDim.x + threadIdx.x;
    if (n >= NA) return;
    float s = 0.f;
    #pragma unroll
    for (int c = 0; c < CM; c++) {
        float v = dict[c * NA + n];
        s += v * v;
    }
    float inv = 1.f / fmaxf(sqrtf(s), 1e-10f);
    #pragma unroll
    for (int c = 0; c < CM; c++) {
        float v = dict[c * NA + n] * inv;
        g_DnT[n * CM + c] = v;
        g_Dn[c * NA + n] = v;
    }
}

// ---------------------------------------------------------------------------
// Kernel 2: Gram matrix G = Dn^T Dn — tiled 128x128, FFMA2, both operands
// from the coalesced [c][n] layout. Grid = 16 CTAs.
// ---------------------------------------------------------------------------
__global__ __launch_bounds__(256) void k_gram() {
    __shared__ float As[CM][128];
    __shared__ float Bs[CM][128];
    int tx = threadIdx.x & 15, ty = threadIdx.x >> 4;
    int i0 = (blockIdx.x >> 2) * 128, j0 = (blockIdx.x & 3) * 128;

    #pragma unroll
    for (int r = 0; r < 8; r++) {
        int idx = r * 256 + threadIdx.x;
        int c = idx >> 5, m4 = (idx & 31) << 2;
        *(float4*)&As[c][m4] = *(const float4*)(g_Dn + c * NA + i0 + m4);
        *(float4*)&Bs[c][m4] = *(const float4*)(g_Dn + c * NA + j0 + m4);
    }
    __syncthreads();

    u64 acc2[8][4];
    #pragma unroll
    for (int i = 0; i < 8; i++)
        #pragma unroll
        for (int j = 0; j < 4; j++) acc2[i][j] = 0ull;

    #pragma unroll
    for (int k = 0; k < CM; k++) {
        float4 a0 = *(float4*)&As[k][ty * 8];
        float4 a1 = *(float4*)&As[k][ty * 8 + 4];
        ulonglong2 bp0 = *(ulonglong2*)&Bs[k][tx * 8];
        ulonglong2 bp1 = *(ulonglong2*)&Bs[k][tx * 8 + 4];
        float ar[8] = {a0.x, a0.y, a0.z, a0.w, a1.x, a1.y, a1.z, a1.w};
        u64 bp[4] = {bp0.x, bp0.y, bp1.x, bp1.y};
        #pragma unroll
        for (int i = 0; i < 8; i++) {
            u64 ad;
            F32X2_DUP(ad, ar[i]);
            #pragma unroll
            for (int j = 0; j < 4; j++)
                F32X2_FMA(acc2[i][j], ad, bp[j]);
        }
    }
    #pragma unroll
    for (int i = 0; i < 8; i++) {
        u64* o = (u64*)&g_G[(size_t)(i0 + ty * 8 + i) * NA + j0 + tx * 8];
        ulonglong2 s0, s1;
        s0.x = acc2[i][0]; s0.y = acc2[i][1];
        s1.x = acc2[i][2]; s1.y = acc2[i][3];
        *(ulonglong2*)o       = s0;
        *(ulonglong2*)(o + 2) = s1;
    }
}

// ---------------------------------------------------------------------------
// Kernel 3: H = X^T Dn. 128x128 tiles, K-tile=32, 8x8 blocking via FFMA2.
// ---------------------------------------------------------------------------
__global__ __launch_bounds__(256, 2) void k_gemm(const float* __restrict__ ze) {
    __shared__ float As[32][128];
    __shared__ float Bs[32][128];
    int tx = threadIdx.x & 15, ty = threadIdx.x >> 4;
    int m0 = blockIdx.y * 128, n0 = blockIdx.x * 128;
    int bb = m0 >> 12;
    int p0 = m0 & (HW - 1);
    const float* zb = ze + (size_t)bb * CHW + p0;

    u64 acc2[8][4];
    #pragma unroll
    for (int i = 0; i < 8; i++)
        #pragma unroll
        for (int j = 0; j < 4; j++) acc2[i][j] = 0ull;

    #pragma unroll
    for (int kk0 = 0; kk0 < CM; kk0 += 32) {
        #pragma unroll
        for (int r = 0; r < 4; r++) {
            int idx = r * 256 + threadIdx.x;
            int kk = idx >> 5, m4 = (idx & 31) << 2;
            *(float4*)&As[kk][m4] = *(const float4*)(zb + (size_t)(kk0 + kk) * HW + m4);
            *(float4*)&Bs[kk][m4] = *(const float4*)(g_Dn + (size_t)(kk0 + kk) * NA + n0 + m4);
        }
        __syncthreads();
        #pragma unroll
        for (int k = 0; k < 32; k++) {
            float4 a0 = *(float4*)&As[k][ty * 8];
            float4 a1 = *(float4*)&As[k][ty * 8 + 4];
            ulonglong2 bp0 = *(ulonglong2*)&Bs[k][tx * 8];
            ulonglong2 bp1 = *(ulonglong2*)&Bs[k][tx * 8 + 4];
            float ar[8] = {a0.x, a0.y, a0.z, a0.w, a1.x, a1.y, a1.z, a1.w};
            u64 bp[4] = {bp0.x, bp0.y, bp1.x, bp1.y};
            #pragma unroll
            for (int i = 0; i < 8; i++) {
                u64 ad;
                F32X2_DUP(ad, ar[i]);
                #pragma unroll
                for (int j = 0; j < 4; j++)
                    F32X2_FMA(acc2[i][j], ad, bp[j]);
            }
        }
        __syncthreads();
    }
    #pragma unroll
    for (int i = 0; i < 8; i++) {
        int m = m0 + ty * 8 + i;
        u64* o = (u64*)&g_H[(size_t)m * NA + n0 + tx * 8];
        ulonglong2 s0, s1;
        s0.x = acc2[i][0]; s0.y = acc2[i][1];
        s1.x = acc2[i][2]; s1.y = acc2[i][3];
        *(ulonglong2*)o       = s0;
        *(ulonglong2*)(o + 2) = s1;
    }
}

// ---------------------------------------------------------------------------
// Kernel 4: OMP. One warp per signal, 4 per CTA. h in registers; cached G
// rows in smem (lane-private slots, no syncs). Sweep row prefetched before
// the solver; solver Gv values come from smem row cache (LDS broadcast).
// ---------------------------------------------------------------------------
__global__ __launch_bounds__(128, 6) void k_omp(float* __restrict__ out_sup,
                                                float* __restrict__ out_cf) {
    __shared__ float rows[4][3][NA];   // 24KB: cached G rows per warp

    const int lane = threadIdx.x & 31;
    const int wid  = threadIdx.x >> 5;
    const int m = blockIdx.x * 4 + wid;
    const float* Hb = g_H + (size_t)m * NA;
    const ulonglong2* Hb2 = (const ulonglong2*)Hb;

    u64   h2[8];          // 16 h values as 8 pairs; pair 2j+q covers elems 4*(lane+32j)+2q+{0,1}
    float Lo[10];         // off-diagonal L rows 1..4 (packed (i-1)i/2+j)
    float Linv[5];        // reciprocal diagonals
    float y[5];
    float gam[5];
    int   sel[5];

    // load h_bar + value-only max tracking (FMNMX with free |.| modifiers)
    float bv = 0.f;
#pragma unroll
    for (int j = 0; j < 4; j++) {
        ulonglong2 v = __ldg(&Hb2[lane + 32 * j]);
        h2[2 * j] = v.x;
        h2[2 * j + 1] = v.y;
        bv = fmaxf(bv, fabsf(u64_lo(v.x)));
        bv = fmaxf(bv, fabsf(u64_hi(v.x)));
        bv = fmaxf(bv, fabsf(u64_lo(v.y)));
        bv = fmaxf(bv, fabsf(u64_hi(v.y)));
    }

#pragma unroll
    for (int k = 1; k <= KS; k++) {
        // ---- warp max value, then lowest-index recovery
        float wmax = __uint_as_float(__reduce_max_sync(FULL, __float_as_uint(bv)));
        int cand = 1 << 30;
#pragma unroll
        for (int j = 3; j >= 0; j--) {        // descending index: lowest wins
            int base = 4 * (lane + 32 * j);
            u64 px = h2[2 * j], py = h2[2 * j + 1];
            if (fabsf(u64_hi(py)) == wmax) cand = base + 3;
            if (fabsf(u64_lo(py)) == wmax) cand = base + 2;
            if (fabsf(u64_hi(px)) == wmax) cand = base + 1;
            if (fabsf(u64_lo(px)) == wmax) cand = base;
        }
        int bi = __reduce_min_sync(FULL, cand);

        const float* Grow = g_G + (size_t)bi * NA;

        // ---- prefetch sweep row right away (covers L2 latency under solver)
        ulonglong2 gvv[4];
        if (k < KS) {
            const ulonglong2* Gr2 = (const ulonglong2*)Grow;
#pragma unroll
            for (int j = 0; j < 4; j++) gvv[j] = __ldg(&Gr2[lane + 32 * j]);
        }

        // true h_bar[bi]: uniform broadcast load, L1-hot
        float hbv = __ldg(Hb + bi);

        // ---- Gv[t] = G[sel_t][bi] from the smem row cache (broadcast LDS)
        float Gv[4];
#pragma unroll
        for (int t = 0; t < 3; t++)
            if (t < k - 1) Gv[t] = rows[wid][t][bi];
        if (k == KS) Gv[3] = __ldg(g_G + (size_t)sel[3] * NA + bi);

        // ---- Cholesky rank-1 extension (divide-free, all lanes uniform)
        if (k > 1) {
            float w[4], ww = 0.f;
#pragma unroll
            for (int i = 0; i < 4; i++) {
                if (i < k - 1) {
                    float a = Gv[i];
#pragma unroll
                    for (int j = 0; j < 4; j++)
                        if (j < i) a -= Lo[(i - 1) * i / 2 + j] * w[j];
                    if (i > 0) a *= Linv[i];
                    w[i] = a;
                    ww += a * a;
                }
            }
            const int r = k - 1;
#pragma unroll
            for (int j = 0; j < 4; j++)
                if (j < r) Lo[(r - 1) * r / 2 + j] = w[j];
            Linv[r] = rsqrtf(fmaxf(1.f - ww, 1e-12f));
        } else {
            Linv[0] = 1.f;
        }
        sel[k - 1] = bi;

        // ---- incremental forward solve: only y[k-1] is new
        {
            const int i = k - 1;
            float a = hbv;
#pragma unroll
            for (int j = 0; j < 4; j++)
                if (j < i) a -= Lo[(i - 1) * i / 2 + j] * y[j];
            y[i] = a * Linv[i];
        }

        // ---- backward solve: L^T g2 = y
        float g2[5];
#pragma unroll
        for (int i = 4; i >= 0; i--) {
            if (i < k) {
                float a = y[i];
#pragma unroll
                for (int j = 0; j < 5; j++)
                    if (j > i && j < k) a -= Lo[(j - 1) * j / 2 + i] * g2[j];
                g2[i] = a * Linv[i];
            }
        }
        float dg[5];
#pragma unroll
        for (int i = 0; i < 5; i++) {
            if (i < k) {
                float old = (i < k - 1) ? gam[i] : 0.f;
                dg[i] = g2[i] - old;
                gam[i] = g2[i];
            }
        }

        // ---- fused packed h update + value-only max tracking
        if (k < KS) {
            u64 ndp[4];
#pragma unroll
            for (int t = 0; t < 4; t++)
                if (t < k) F32X2_DUP(ndp[t], -dg[t]);
            bv = 0.f;
#pragma unroll
            for (int j = 0; j < 4; j++) {
                int fi = 4 * (lane + 32 * j);
                if (k - 1 < 3)
                    *(ulonglong2*)&rows[wid][k - 1][fi] = gvv[j];
                u64 a0, a1;
                F32X2_MUL(a0, ndp[k - 1], gvv[j].x);
                F32X2_MUL(a1, ndp[k - 1], gvv[j].y);
#pragma unroll
                for (int t = 0; t < 3; t++) {
                    if (t < k - 1) {
                        ulonglong2 rv = *(const ulonglong2*)&rows[wid][t][fi];
                        F32X2_FMA(a0, ndp[t], rv.x);
                        F32X2_FMA(a1, ndp[t], rv.y);
                    }
                }
                u64 hn0, hn1;
                F32X2_ADD(hn0, h2[2 * j], a0);
                F32X2_ADD(hn1, h2[2 * j + 1], a1);
                h2[2 * j] = hn0;
                h2[2 * j + 1] = hn1;
                bv = fmaxf(bv, fabsf(u64_lo(hn0)));
                bv = fmaxf(bv, fabsf(u64_hi(hn0)));
                bv = fmaxf(bv, fabsf(u64_lo(hn1)));
                bv = fmaxf(bv, fabsf(u64_hi(hn1)));
            }
        }
    }

    // ---- outputs (values are warp-uniform)
    if (lane < KS) {
        float s = (lane == 0) ? (float)sel[0] :
                  (lane == 1) ? (float)sel[1] :
                  (lane == 2) ? (float)sel[2] :
                  (lane == 3) ? (float)sel[3] : (float)sel[4];
        float c = (lane == 0) ? gam[0] :
                  (lane == 1) ? gam[1] :
                  (lane == 2) ? gam[2] :
                  (lane == 3) ? gam[3] : gam[4];
        out_sup[(size_t)m * KS + lane] = s;
        out_cf[(size_t)m * KS + lane]  = c;
    }
}

// ---------------------------------------------------------------------------
// Kernel 5: coalesced reconstruction + squared error
// ---------------------------------------------------------------------------
__global__ __launch_bounds__(256) void k_recon(const float* __restrict__ ze,
                                               const float* __restrict__ sup,
                                               const float* __restrict__ cf,
                                               float* __restrict__ out_zdl) {
    __shared__ float tile[CM][33];
    __shared__ float red[256];

    int m0 = blockIdx.x * 32;
    int b  = m0 >> 12;
    int p0 = m0 & (HW - 1);
    int wid = threadIdx.x >> 5, lane = threadIdx.x & 31;

    for (int s = wid; s < 32; s += 8) {
        int m = m0 + s;
        int   si[KS];
        float ci[KS];
        #pragma unroll
        for (int t = 0; t < KS; t++) {
            si[t] = (int)sup[(size_t)m * KS + t];
            ci[t] = cf[(size_t)m * KS + t];
        }
        #pragma unroll
        for (int half = 0; half < 2; half++) {
            int c = lane + 32 * half;
            float r = 0.f;
            #pragma unroll
            for (int t = 0; t < KS; t++)
                r = fmaf(ci[t], g_DnT[si[t] * CM + c], r);
            tile[c][s] = r;
        }
    }
    __syncthreads();

    int p  = threadIdx.x & 31;
    int cb = threadIdx.x >> 5;
    float err = 0.f;
    #pragma unroll
    for (int j = 0; j < 8; j++) {
        int c = cb * 8 + j;
        size_t zi = (size_t)b * CHW + (size_t)c * HW + p0 + p;
        float r = tile[c][p];
        float x = ze[zi];
        float d = r - x;
        err += d * d;
        out_zdl[zi] = r;
    }
    red[threadIdx.x] = err;
    __syncthreads();
    for (int o = 128; o; o >>= 1) {
        if (threadIdx.x < o) red[threadIdx.x] += red[threadIdx.x + o];
        __syncthreads();
    }
    if (threadIdx.x == 0) g_partial[blockIdx.x] = red[0];
}

// ---------------------------------------------------------------------------
// Kernel 6: deterministic loss reduction. loss = 1.25 * MSE
// ---------------------------------------------------------------------------
__global__ void k_loss(float* __restrict__ out_loss) {
    __shared__ float red[1024];
    red[threadIdx.x] = g_partial[threadIdx.x];
    __syncthreads();
    for (int o = 512; o; o >>= 1) {
        if (threadIdx.x < o) red[threadIdx.x] += red[threadIdx.x + o];
        __syncthreads();
    }
    if (threadIdx.x == 0) out_loss[0] = 1.25f * red[0] / NUMEL;
}

// ---------------------------------------------------------------------------
extern "C" void kernel_launch(void* const* d_in, const int* in_sizes, int n_in,
                              void* d_out, int out_size) {
    const float* ze   = (const float*)d_in[0];
    const float* dict = (const float*)d_in[1];
    float* out = (float*)d_out;
    float* out_zdl  = out;
    float* out_loss = out + 2097152;
    float* out_sup  = out + 2097153;
    float* out_cf   = out + 2097153 + 163840;

    k_norm<<<2, 256>>>(dict);
    k_gram<<<16, 256>>>();
    dim3 g(NA / 128, MS / 128);
    k_gemm<<<g, 256>>>(ze);
    k_omp<<<MS / 4, 128>>>(out_sup, out_cf);
    k_recon<<<MS / 32, 256>>>(ze, out_sup, out_cf, out_zdl);
    k_loss<<<1, 1024>>>(out_loss);
}

// round 9
// speedup vs baseline: 1.1572x; 1.0527x over previous
#include <cuda_runtime.h>
#include <cuda_bf16.h>
#include <math.h>

#define CM 64
#define NA 512
#define MS 32768
#define KS 5
#define HW 4096
#define CHW 262144
#define NUMEL 2097152.0f
#define FULL 0xffffffffu

typedef unsigned long long u64;

// packed fp32x2 helpers (sm_103a; ptxas never emits these on its own)
#define F32X2_FMA(d, a, b) \
    asm("fma.rn.f32x2 %0, %1, %2, %0;" : "+l"(d) : "l"(a), "l"(b))
#define F32X2_MUL(d, a, b) \
    asm("mul.rn.f32x2 %0, %1, %2;" : "=l"(d) : "l"(a), "l"(b))
#define F32X2_ADD(d, a, b) \
    asm("add.rn.f32x2 %0, %1, %2;" : "=l"(d) : "l"(a), "l"(b))
#define F32X2_DUP(d, x) \
    asm("mov.b64 %0, {%1, %1};" : "=l"(d) : "r"(__float_as_uint(x)))

__device__ __forceinline__ float u64_lo(u64 v) { return __uint_as_float((unsigned)v); }
__device__ __forceinline__ float u64_hi(u64 v) { return __uint_as_float((unsigned)(v >> 32)); }

__device__ float g_DnT[NA * CM];
__device__ float g_Dn[CM * NA];
__device__ float g_G[NA * NA];
__device__ float g_H[(size_t)MS * NA];
__device__ float g_partial[1024];

// ---------------------------------------------------------------------------
// Kernel 1: Gram matrix G = Dn^T Dn with in-kernel normalization of the raw
// dictionary. The 4 CTAs with j-block 0 also emit g_Dn / g_DnT side outputs.
// ---------------------------------------------------------------------------
__global__ __launch_bounds__(256) void k_gram(const float* __restrict__ dict) {
    __shared__ float As[CM][128];
    __shared__ float Bs[CM][128];
    __shared__ float invI[128], invJ[128];
    int tx = threadIdx.x & 15, ty = threadIdx.x >> 4;
    int i0 = (blockIdx.x >> 2) * 128, j0 = (blockIdx.x & 3) * 128;

    // column inverse norms (threads 0..127 -> I cols, 128..255 -> J cols)
    {
        int col = threadIdx.x & 127;
        int n = (threadIdx.x < 128) ? (i0 + col) : (j0 + col);
        float s = 0.f;
        #pragma unroll
        for (int c = 0; c < CM; c++) {
            float v = dict[c * NA + n];
            s += v * v;
        }
        float inv = 1.f / fmaxf(sqrtf(s), 1e-10f);
        if (threadIdx.x < 128) invI[col] = inv; else invJ[col] = inv;
    }
    __syncthreads();

    // load normalized tiles
    #pragma unroll
    for (int r = 0; r < 8; r++) {
        int idx = r * 256 + threadIdx.x;
        int c = idx >> 5, m4 = (idx & 31) << 2;
        float4 a = *(const float4*)(dict + c * NA + i0 + m4);
        a.x *= invI[m4]; a.y *= invI[m4 + 1]; a.z *= invI[m4 + 2]; a.w *= invI[m4 + 3];
        *(float4*)&As[c][m4] = a;
        float4 b = *(const float4*)(dict + c * NA + j0 + m4);
        b.x *= invJ[m4]; b.y *= invJ[m4 + 1]; b.z *= invJ[m4 + 2]; b.w *= invJ[m4 + 3];
        *(float4*)&Bs[c][m4] = b;
    }
    __syncthreads();

    u64 acc2[8][4];
    #pragma unroll
    for (int i = 0; i < 8; i++)
        #pragma unroll
        for (int j = 0; j < 4; j++) acc2[i][j] = 0ull;

    #pragma unroll
    for (int k = 0; k < CM; k++) {
        float4 a0 = *(float4*)&As[k][ty * 8];
        float4 a1 = *(float4*)&As[k][ty * 8 + 4];
        ulonglong2 bp0 = *(ulonglong2*)&Bs[k][tx * 8];
        ulonglong2 bp1 = *(ulonglong2*)&Bs[k][tx * 8 + 4];
        float ar[8] = {a0.x, a0.y, a0.z, a0.w, a1.x, a1.y, a1.z, a1.w};
        u64 bp[4] = {bp0.x, bp0.y, bp1.x, bp1.y};
        #pragma unroll
        for (int i = 0; i < 8; i++) {
            u64 ad;
            F32X2_DUP(ad, ar[i]);
            #pragma unroll
            for (int j = 0; j < 4; j++)
                F32X2_FMA(acc2[i][j], ad, bp[j]);
        }
    }
    #pragma unroll
    for (int i = 0; i < 8; i++) {
        u64* o = (u64*)&g_G[(size_t)(i0 + ty * 8 + i) * NA + j0 + tx * 8];
        ulonglong2 s0, s1;
        s0.x = acc2[i][0]; s0.y = acc2[i][1];
        s1.x = acc2[i][2]; s1.y = acc2[i][3];
        *(ulonglong2*)o       = s0;
        *(ulonglong2*)(o + 2) = s1;
    }

    // side outputs: normalized dictionary in both layouts (4 CTAs only)
    if ((blockIdx.x & 3) == 0) {
        for (int idx = threadIdx.x; idx < CM * 128; idx += 256) {
            int c = idx >> 7, x = idx & 127;          // coalesced in x
            g_Dn[c * NA + i0 + x] = As[c][x];
        }
        for (int idx = threadIdx.x; idx < 128 * CM; idx += 256) {
            int x = idx >> 6, c = idx & 63;           // coalesced in c
            g_DnT[(i0 + x) * CM + c] = dict[c * NA + i0 + x] * invI[x];
        }
    }
}

// ---------------------------------------------------------------------------
// Kernel 2: H = X^T Dn. 128x128 tiles, K-tile=32, 8x8 blocking via FFMA2.
// ---------------------------------------------------------------------------
__global__ __launch_bounds__(256, 2) void k_gemm(const float* __restrict__ ze) {
    __shared__ float As[32][128];
    __shared__ float Bs[32][128];
    int tx = threadIdx.x & 15, ty = threadIdx.x >> 4;
    int m0 = blockIdx.y * 128, n0 = blockIdx.x * 128;
    int bb = m0 >> 12;
    int p0 = m0 & (HW - 1);
    const float* zb = ze + (size_t)bb * CHW + p0;

    u64 acc2[8][4];
    #pragma unroll
    for (int i = 0; i < 8; i++)
        #pragma unroll
        for (int j = 0; j < 4; j++) acc2[i][j] = 0ull;

    #pragma unroll
    for (int kk0 = 0; kk0 < CM; kk0 += 32) {
        #pragma unroll
        for (int r = 0; r < 4; r++) {
            int idx = r * 256 + threadIdx.x;
            int kk = idx >> 5, m4 = (idx & 31) << 2;
            *(float4*)&As[kk][m4] = *(const float4*)(zb + (size_t)(kk0 + kk) * HW + m4);
            *(float4*)&Bs[kk][m4] = *(const float4*)(g_Dn + (size_t)(kk0 + kk) * NA + n0 + m4);
        }
        __syncthreads();
        #pragma unroll
        for (int k = 0; k < 32; k++) {
            float4 a0 = *(float4*)&As[k][ty * 8];
            float4 a1 = *(float4*)&As[k][ty * 8 + 4];
            ulonglong2 bp0 = *(ulonglong2*)&Bs[k][tx * 8];
            ulonglong2 bp1 = *(ulonglong2*)&Bs[k][tx * 8 + 4];
            float ar[8] = {a0.x, a0.y, a0.z, a0.w, a1.x, a1.y, a1.z, a1.w};
            u64 bp[4] = {bp0.x, bp0.y, bp1.x, bp1.y};
            #pragma unroll
            for (int i = 0; i < 8; i++) {
                u64 ad;
                F32X2_DUP(ad, ar[i]);
                #pragma unroll
                for (int j = 0; j < 4; j++)
                    F32X2_FMA(acc2[i][j], ad, bp[j]);
            }
        }
        __syncthreads();
    }
    #pragma unroll
    for (int i = 0; i < 8; i++) {
        int m = m0 + ty * 8 + i;
        u64* o = (u64*)&g_H[(size_t)m * NA + n0 + tx * 8];
        ulonglong2 s0, s1;
        s0.x = acc2[i][0]; s0.y = acc2[i][1];
        s1.x = acc2[i][2]; s1.y = acc2[i][3];
        *(ulonglong2*)o       = s0;
        *(ulonglong2*)(o + 2) = s1;
    }
}

// ---------------------------------------------------------------------------
// Kernel 3: OMP + coalesced reconstruction. 8 warps/CTA, 4 signals per warp
// (32 consecutive pixels per CTA). Recon values held in registers during the
// OMP loop; the G-row smem cache is aliased as the transpose tile afterwards.
// ---------------------------------------------------------------------------
__global__ __launch_bounds__(256, 3) void k_omp(const float* __restrict__ ze,
                                                float* __restrict__ out_zdl,
                                                float* __restrict__ out_sup,
                                                float* __restrict__ out_cf) {
    __shared__ float rows[8][3][NA];   // 48KB; dead after OMP, reused as tile

    const int lane = threadIdx.x & 31;
    const int wid  = threadIdx.x >> 5;
    const int m0 = blockIdx.x * 32;

    float recA[4], recB[4];

    #pragma unroll 1
    for (int it = 0; it < 4; it++) {
        const int m = m0 + wid * 4 + it;
        const float* Hb = g_H + (size_t)m * NA;
        const ulonglong2* Hb2 = (const ulonglong2*)Hb;

        u64   h2[8];
        float Lo[10];
        float Linv[5];
        float y[5];
        float gam[5];
        int   sel[5];

        float bv = 0.f;
#pragma unroll
        for (int j = 0; j < 4; j++) {
            ulonglong2 v = __ldg(&Hb2[lane + 32 * j]);
            h2[2 * j] = v.x;
            h2[2 * j + 1] = v.y;
            bv = fmaxf(bv, fabsf(u64_lo(v.x)));
            bv = fmaxf(bv, fabsf(u64_hi(v.x)));
            bv = fmaxf(bv, fabsf(u64_lo(v.y)));
            bv = fmaxf(bv, fabsf(u64_hi(v.y)));
        }

#pragma unroll
        for (int k = 1; k <= KS; k++) {
            float wmax = __uint_as_float(__reduce_max_sync(FULL, __float_as_uint(bv)));
            int cand = 1 << 30;
#pragma unroll
            for (int j = 3; j >= 0; j--) {
                int base = 4 * (lane + 32 * j);
                u64 px = h2[2 * j], py = h2[2 * j + 1];
                if (fabsf(u64_hi(py)) == wmax) cand = base + 3;
                if (fabsf(u64_lo(py)) == wmax) cand = base + 2;
                if (fabsf(u64_hi(px)) == wmax) cand = base + 1;
                if (fabsf(u64_lo(px)) == wmax) cand = base;
            }
            int bi = __reduce_min_sync(FULL, cand);

            const float* Grow = g_G + (size_t)bi * NA;

            // prefetch sweep row (covers L2 latency under the solver)
            ulonglong2 gvv[4];
            if (k < KS) {
                const ulonglong2* Gr2 = (const ulonglong2*)Grow;
#pragma unroll
                for (int j = 0; j < 4; j++) gvv[j] = __ldg(&Gr2[lane + 32 * j]);
            }

            float hbv = __ldg(Hb + bi);

            float Gv[4];
#pragma unroll
            for (int t = 0; t < 3; t++)
                if (t < k - 1) Gv[t] = rows[wid][t][bi];
            if (k == KS) Gv[3] = __ldg(g_G + (size_t)sel[3] * NA + bi);

            if (k > 1) {
                float w[4], ww = 0.f;
#pragma unroll
                for (int i = 0; i < 4; i++) {
                    if (i < k - 1) {
                        float a = Gv[i];
#pragma unroll
                        for (int j = 0; j < 4; j++)
                            if (j < i) a -= Lo[(i - 1) * i / 2 + j] * w[j];
                        if (i > 0) a *= Linv[i];
                        w[i] = a;
                        ww += a * a;
                    }
                }
                const int r = k - 1;
#pragma unroll
                for (int j = 0; j < 4; j++)
                    if (j < r) Lo[(r - 1) * r / 2 + j] = w[j];
                Linv[r] = rsqrtf(fmaxf(1.f - ww, 1e-12f));
            } else {
                Linv[0] = 1.f;
            }
            sel[k - 1] = bi;

            {
                const int i = k - 1;
                float a = hbv;
#pragma unroll
                for (int j = 0; j < 4; j++)
                    if (j < i) a -= Lo[(i - 1) * i / 2 + j] * y[j];
                y[i] = a * Linv[i];
            }

            float g2[5];
#pragma unroll
            for (int i = 4; i >= 0; i--) {
                if (i < k) {
                    float a = y[i];
#pragma unroll
                    for (int j = 0; j < 5; j++)
                        if (j > i && j < k) a -= Lo[(j - 1) * j / 2 + i] * g2[j];
                    g2[i] = a * Linv[i];
                }
            }
            float dg[5];
#pragma unroll
            for (int i = 0; i < 5; i++) {
                if (i < k) {
                    float old = (i < k - 1) ? gam[i] : 0.f;
                    dg[i] = g2[i] - old;
                    gam[i] = g2[i];
                }
            }

            if (k < KS) {
                u64 ndp[4];
#pragma unroll
                for (int t = 0; t < 4; t++)
                    if (t < k) F32X2_DUP(ndp[t], -dg[t]);
                bv = 0.f;
#pragma unroll
                for (int j = 0; j < 4; j++) {
                    int fi = 4 * (lane + 32 * j);
                    if (k - 1 < 3)
                        *(ulonglong2*)&rows[wid][k - 1 < 3 ? k - 1 : 0][fi] = gvv[j];
                    u64 a0, a1;
                    F32X2_MUL(a0, ndp[k - 1], gvv[j].x);
                    F32X2_MUL(a1, ndp[k - 1], gvv[j].y);
#pragma unroll
                    for (int t = 0; t < 3; t++) {
                        if (t < k - 1) {
                            ulonglong2 rv = *(const ulonglong2*)&rows[wid][t][fi];
                            F32X2_FMA(a0, ndp[t], rv.x);
                            F32X2_FMA(a1, ndp[t], rv.y);
                        }
                    }
                    u64 hn0, hn1;
                    F32X2_ADD(hn0, h2[2 * j], a0);
                    F32X2_ADD(hn1, h2[2 * j + 1], a1);
                    h2[2 * j] = hn0;
                    h2[2 * j + 1] = hn1;
                    bv = fmaxf(bv, fabsf(u64_lo(hn0)));
                    bv = fmaxf(bv, fabsf(u64_hi(hn0)));
                    bv = fmaxf(bv, fabsf(u64_lo(hn1)));
                    bv = fmaxf(bv, fabsf(u64_hi(hn1)));
                }
            }
        }

        // support / coeff outputs (values are warp-uniform)
        if (lane < KS) {
            float s = (lane == 0) ? (float)sel[0] :
                      (lane == 1) ? (float)sel[1] :
                      (lane == 2) ? (float)sel[2] :
                      (lane == 3) ? (float)sel[3] : (float)sel[4];
            float c = (lane == 0) ? gam[0] :
                      (lane == 1) ? gam[1] :
                      (lane == 2) ? gam[2] :
                      (lane == 3) ? gam[3] : gam[4];
            out_sup[(size_t)m * KS + lane] = s;
            out_cf[(size_t)m * KS + lane]  = c;
        }

        // reconstruction into registers (coalesced DnT reads, L2-hot)
        {
            float r0 = 0.f, r1 = 0.f;
#pragma unroll
            for (int t = 0; t < KS; t++) {
                const float* dn = g_DnT + sel[t] * CM;
                r0 = fmaf(gam[t], __ldg(dn + lane), r0);
                r1 = fmaf(gam[t], __ldg(dn + lane + 32), r1);
            }
            recA[it] = r0;
            recB[it] = r1;
        }
    }

    // ---- alias the dead rows cache as transpose tile + reduction scratch
    __syncthreads();
    float* sm = &rows[0][0][0];
    float (*tile)[33] = (float (*)[33])sm;          // 64 x 33 floats
    float* red = sm + CM * 33;                      // 256 floats
#pragma unroll
    for (int it = 0; it < 4; it++) {
        int s = wid * 4 + it;
        tile[lane][s]      = recA[it];
        tile[lane + 32][s] = recB[it];
    }
    __syncthreads();

    // ---- coalesced write phase: 256 threads, 8 channels x 1 pixel each
    int b  = m0 >> 12;
    int p0 = m0 & (HW - 1);
    int p  = threadIdx.x & 31;
    int cb = threadIdx.x >> 5;
    float err = 0.f;
#pragma unroll
    for (int j = 0; j < 8; j++) {
        int c = cb * 8 + j;
        size_t zi = (size_t)b * CHW + (size_t)c * HW + p0 + p;
        float r = tile[c][p];
        float x = ze[zi];
        float d = r - x;
        err += d * d;
        out_zdl[zi] = r;
    }
    red[threadIdx.x] = err;
    __syncthreads();
    for (int o = 128; o; o >>= 1) {
        if (threadIdx.x < o) red[threadIdx.x] += red[threadIdx.x + o];
        __syncthreads();
    }
    if (threadIdx.x == 0) g_partial[blockIdx.x] = red[0];
}

// ---------------------------------------------------------------------------
// Kernel 4: deterministic loss reduction. loss = 1.25 * MSE
// ---------------------------------------------------------------------------
__global__ void k_loss(float* __restrict__ out_loss) {
    __shared__ float red[1024];
    red[threadIdx.x] = g_partial[threadIdx.x];
    __syncthreads();
    for (int o = 512; o; o >>= 1) {
        if (threadIdx.x < o) red[threadIdx.x] += red[threadIdx.x + o];
        __syncthreads();
    }
    if (threadIdx.x == 0) out_loss[0] = 1.25f * red[0] / NUMEL;
}

// ---------------------------------------------------------------------------
extern "C" void kernel_launch(void* const* d_in, const int* in_sizes, int n_in,
                              void* d_out, int out_size) {
    const float* ze   = (const float*)d_in[0];
    const float* dict = (const float*)d_in[1];
    float* out = (float*)d_out;
    float* out_zdl  = out;
    float* out_loss = out + 2097152;
    float* out_sup  = out + 2097153;
    float* out_cf   = out + 2097153 + 163840;

    k_gram<<<16, 256>>>(dict);
    dim3 g(NA / 128, MS / 128);
    k_gemm<<<g, 256>>>(ze);
    k_omp<<<MS / 32, 256>>>(ze, out_zdl, out_sup, out_cf);
    k_loss<<<1, 1024>>>(out_loss);
}